// round 6
// baseline (speedup 1.0000x reference)
#include <cuda_runtime.h>
#include <stdint.h>

// Segmented max pooling — bucketed gather with self-resetting scratch:
//   1) fill:   pos = atomicAdd(count[seg]); pos<CAP -> bucket, else spill list
//   2) gather: 1 warp/segment, max over bucket rows (+inline spill scan),
//              resets count[seg]=0; last block resets spill/done counters.
// All __device__ scratch starts zero and is returned to zero each call,
// so no zero-init kernel is needed (deterministic across graph replays).
// Fallback: generic atomic-scatter path for shapes beyond static scratch.

#define MAX_SEG   (1 << 18)   // 262144
#define MAX_ROWS  (1 << 20)   // 1048576
#define CAP        32
#define NEG_INF __int_as_float(0xff800000)

__device__ int g_counts[MAX_SEG];           // zero at entry, reset by gather
__device__ int g_bucket[MAX_SEG * CAP];     // 32 MB scratch
__device__ int g_spill_rows[MAX_ROWS];
__device__ int g_spill_n;                   // zero at entry, reset by gather
__device__ unsigned g_done;                 // gather block-done counter

// ---------------- bucketed gather path ----------------

__global__ void fill_kernel(const int4* __restrict__ vt_map4, int n_rows4, int vt_out) {
    int i = blockIdx.x * blockDim.x + threadIdx.x;
    if (i >= n_rows4) return;
    int4 m = __ldg(&vt_map4[i]);
    int rows[4] = {4 * i, 4 * i + 1, 4 * i + 2, 4 * i + 3};
    int segs[4] = {m.x, m.y, m.z, m.w};
    #pragma unroll
    for (int k = 0; k < 4; k++) {
        int seg = segs[k];
        if (seg < 0 || seg >= vt_out) continue;
        int pos = atomicAdd(&g_counts[seg], 1);
        if (pos < CAP) {
            g_bucket[(size_t)seg * CAP + pos] = rows[k];
        } else {
            int s = atomicAdd(&g_spill_n, 1);
            g_spill_rows[s] = rows[k];
        }
    }
}

// One warp per segment; C == 64: lane holds channels {2l, 2l+1} as float2.
__global__ void gather_max_kernel(const float2* __restrict__ in2,
                                  const int* __restrict__ vt_map,
                                  float2* __restrict__ out2, int nseg) {
    int warp = (blockIdx.x * blockDim.x + threadIdx.x) >> 5;
    int lane = threadIdx.x & 31;
    if (warp < nseg) {
        int cnt = g_counts[warp];
        g_counts[warp] = 0;                       // self-reset for next call
        int use = cnt < CAP ? cnt : CAP;
        const int* __restrict__ bkt = g_bucket + (size_t)warp * CAP;
        float2 acc = make_float2(NEG_INF, NEG_INF);
        int j = 0;
        for (; j + 4 <= use; j += 4) {
            int r0 = __ldg(&bkt[j]);
            int r1 = __ldg(&bkt[j + 1]);
            int r2 = __ldg(&bkt[j + 2]);
            int r3 = __ldg(&bkt[j + 3]);
            float2 a = __ldcs(&in2[(size_t)r0 * 32 + lane]);
            float2 b = __ldcs(&in2[(size_t)r1 * 32 + lane]);
            float2 c = __ldcs(&in2[(size_t)r2 * 32 + lane]);
            float2 d = __ldcs(&in2[(size_t)r3 * 32 + lane]);
            acc.x = fmaxf(fmaxf(acc.x, fmaxf(a.x, b.x)), fmaxf(c.x, d.x));
            acc.y = fmaxf(fmaxf(acc.y, fmaxf(a.y, b.y)), fmaxf(c.y, d.y));
        }
        if (j + 2 <= use) {
            int r0 = __ldg(&bkt[j]);
            int r1 = __ldg(&bkt[j + 1]);
            float2 a = __ldcs(&in2[(size_t)r0 * 32 + lane]);
            float2 b = __ldcs(&in2[(size_t)r1 * 32 + lane]);
            acc.x = fmaxf(acc.x, fmaxf(a.x, b.x));
            acc.y = fmaxf(acc.y, fmaxf(a.y, b.y));
            j += 2;
        }
        if (j < use) {
            int r0 = __ldg(&bkt[j]);
            float2 a = __ldcs(&in2[(size_t)r0 * 32 + lane]);
            acc.x = fmaxf(acc.x, a.x);
            acc.y = fmaxf(acc.y, a.y);
        }
        if (cnt > CAP) {
            // Overflow (statistically never): scan spill list for our segment.
            int sn = g_spill_n;
            for (int e = 0; e < sn; e++) {
                int row = g_spill_rows[e];
                if (__ldg(&vt_map[row]) == warp) {
                    float2 a = __ldcs(&in2[(size_t)row * 32 + lane]);
                    acc.x = fmaxf(acc.x, a.x);
                    acc.y = fmaxf(acc.y, a.y);
                }
            }
        }
        if (cnt == 0) acc = make_float2(0.0f, 0.0f);
        __stcs(&out2[(size_t)warp * 32 + lane], acc);
    }
    // Last block resets the shared counters for the next invocation.
    __syncthreads();
    if (threadIdx.x == 0) {
        unsigned prev = atomicAdd(&g_done, 1u);
        if (prev == gridDim.x - 1) {
            g_spill_n = 0;
            g_done = 0;
        }
    }
}

// ---------------- fallback scatter path (generic) ----------------

__device__ __forceinline__ unsigned fkey(float f) {
    unsigned b = __float_as_uint(f);
    return (b & 0x80000000u) ? ~b : (b | 0x80000000u);
}
__device__ __forceinline__ float fdecode(unsigned k) {
    unsigned b = (k & 0x80000000u) ? (k & 0x7FFFFFFFu) : ~k;
    return __uint_as_float(b);
}
#define INIT_KEY 0x007FFFFFu

__global__ void init_out_kernel(unsigned* out, long n) {
    long i = blockIdx.x * (long)blockDim.x + threadIdx.x;
    long stride = gridDim.x * (long)blockDim.x;
    for (; i < n; i += stride) out[i] = INIT_KEY;
}

__global__ void scatter_max_kernel(const float* __restrict__ in,
                                   const int* __restrict__ vt_map,
                                   unsigned* __restrict__ out,
                                   long n_total, int C, int vt_out) {
    long i = blockIdx.x * (long)blockDim.x + threadIdx.x;
    long stride = gridDim.x * (long)blockDim.x;
    for (; i < n_total; i += stride) {
        long row = i / C;
        int  c   = (int)(i - row * C);
        int seg = vt_map[row];
        if (seg < 0 || seg >= vt_out) continue;
        atomicMax(out + (size_t)seg * C + c, fkey(in[i]));
    }
}

__global__ void fixup_kernel(unsigned* __restrict__ out, long n) {
    long i = blockIdx.x * (long)blockDim.x + threadIdx.x;
    long stride = gridDim.x * (long)blockDim.x;
    for (; i < n; i += stride) {
        unsigned k = out[i];
        float f = (k == INIT_KEY) ? 0.0f : fdecode(k);
        out[i] = __float_as_uint(f);
    }
}

// ---------------- launcher ----------------

extern "C" void kernel_launch(void* const* d_in, const int* in_sizes, int n_in,
                              void* d_out, int out_size) {
    const float* inputs = (const float*)d_in[0];
    // d_in[1] = vt_replace (unused for max pooling)
    const int*   vt_map = (const int*)d_in[2];

    long n_in_elems = in_sizes[0];                 // N_IN * C
    int  n_rows     = in_sizes[2];                 // N_IN
    int  C          = (int)(n_in_elems / n_rows);  // 64
    int  vt_out     = out_size / C;                // 262144

    const int TPB = 256;

    if (C == 64 && vt_out <= MAX_SEG && n_rows <= MAX_ROWS && (n_rows % 4) == 0) {
        int nseg = vt_out;
        int n_rows4 = n_rows / 4;

        fill_kernel<<<(n_rows4 + TPB - 1) / TPB, TPB>>>((const int4*)vt_map,
                                                        n_rows4, vt_out);

        int warps_per_block = TPB / 32;
        int gblocks = (nseg + warps_per_block - 1) / warps_per_block;
        gather_max_kernel<<<gblocks, TPB>>>((const float2*)inputs, vt_map,
                                            (float2*)d_out, nseg);
    } else {
        long out_elems = (long)out_size;
        int blocks = 148 * 16;
        init_out_kernel<<<blocks, TPB>>>((unsigned*)d_out, out_elems);
        scatter_max_kernel<<<blocks * 2, TPB>>>(inputs, vt_map,
                                                (unsigned*)d_out, n_in_elems, C, vt_out);
        fixup_kernel<<<blocks, TPB>>>((unsigned*)d_out, out_elems);
    }
}